// round 3
// baseline (speedup 1.0000x reference)
#include <cuda_runtime.h>
#include <math_constants.h>

#define N_PTS 16384
#define C_DIM 64
#define K_NN 16

typedef unsigned long long u64;

__device__ __forceinline__ u64 pack2(float x, float y) {
    u64 r; asm("mov.b64 %0, {%1, %2};" : "=l"(r) : "f"(x), "f"(y)); return r;
}
__device__ __forceinline__ void ffma2(u64& d, u64 a, u64 b) {
    asm("fma.rn.f32x2 %0, %1, %2, %0;" : "+l"(d) : "l"(a), "l"(b));
}
__device__ __forceinline__ float2 unpack2(u64 v) {
    float2 f; asm("mov.b64 {%0, %1}, %2;" : "=f"(f.x), "=f"(f.y) : "l"(v)); return f;
}

__device__ float g_norms[N_PTS];
__device__ int   g_knn[N_PTS * K_NN];

// ---------------------------------------------------------------------------
// Kernel 0: squared norms
// ---------------------------------------------------------------------------
__global__ __launch_bounds__(256) void norms_kernel(const float* __restrict__ x) {
    int i = blockIdx.x * 256 + threadIdx.x;
    const float4* xv = (const float4*)(x + (size_t)i * C_DIM);
    float s = 0.f;
#pragma unroll
    for (int d = 0; d < 16; ++d) {
        float4 v = xv[d];
        s += v.x * v.x + v.y * v.y + v.z * v.z + v.w * v.w;
    }
    g_norms[i] = s;
}

// ---------------------------------------------------------------------------
// Kernel 1: fused distance + top-16 selection, packed f32x2 FMA.
// 1 thread per query; x_q in 32 packed b64 regs; candidates broadcast via LDS.
// ---------------------------------------------------------------------------
#define QT 128
#define JT 128

__global__ __launch_bounds__(128) void knn_kernel(const float* __restrict__ x) {
    __shared__ float4 sc[JT * 16];   // candidate tile, 32 KB (linear layout)
    __shared__ float  sn[JT];

    int t = threadIdx.x;
    int q = blockIdx.x * QT + t;

    // x_q as 32 packed f32x2 values (loaded 128-bit at a time)
    u64 xq[32];
    const ulonglong2* xv = (const ulonglong2*)(x + (size_t)q * C_DIM);
#pragma unroll
    for (int d = 0; d < 16; ++d) {
        ulonglong2 v = xv[d];
        xq[2 * d] = v.x; xq[2 * d + 1] = v.y;
    }
    float nq = g_norms[q];

    float bd[16];
    int   bi[16];
#pragma unroll
    for (int s = 0; s < 16; ++s) { bd[s] = CUDART_INF_F; bi[s] = 0; }

    for (int jt = 0; jt < N_PTS; jt += JT) {
        __syncthreads();
        const float4* src = (const float4*)(x + (size_t)jt * C_DIM);
#pragma unroll
        for (int i = 0; i < 16; ++i) sc[t + i * 128] = src[t + i * 128]; // coalesced, conflict-free
        sn[t] = g_norms[jt + t];
        __syncthreads();

#pragma unroll 1
        for (int j = 0; j < JT; ++j) {
            const ulonglong2* c = (const ulonglong2*)(sc + j * 16);  // broadcast
            u64 a0 = 0, a1 = 0, a2 = 0, a3 = 0;
#pragma unroll
            for (int d = 0; d < 16; d += 2) {
                ulonglong2 c0 = c[d];
                ulonglong2 c1 = c[d + 1];
                ffma2(a0, xq[2 * d],     c0.x);
                ffma2(a1, xq[2 * d + 1], c0.y);
                ffma2(a2, xq[2 * d + 2], c1.x);
                ffma2(a3, xq[2 * d + 3], c1.y);
            }
            float2 f0 = unpack2(a0), f1 = unpack2(a1), f2 = unpack2(a2), f3 = unpack2(a3);
            float dot = ((f0.x + f0.y) + (f1.x + f1.y)) + ((f2.x + f2.y) + (f3.x + f3.y));
            float d2 = nq + sn[j] - 2.0f * dot;
            int gj = jt + j;
            if (d2 < bd[15] && gj != q) {
                float cd = d2; int ci = gj;
#pragma unroll
                for (int s = 0; s < 16; ++s) {
                    if (cd < bd[s]) {
                        float td = bd[s]; bd[s] = cd; cd = td;
                        int   ti = bi[s]; bi[s] = ci; ci = ti;
                    }
                }
            }
        }
    }
#pragma unroll
    for (int s = 0; s < 16; ++s) g_knn[q * K_NN + s] = bi[s];
}

// ---------------------------------------------------------------------------
// Kernel 2: gather + edge-MLP + relu + max over K + pixel-shuffle store.
// Packed f32x2 accumulators over output-column pairs; W resident in smem.
// ---------------------------------------------------------------------------
#define MLP_SMEM_FLOATS (32768 + 8 * 2048)   // W(128x256) + 8 warp feat tiles

__global__ __launch_bounds__(256) void mlp_kernel(const float* __restrict__ x,
                                                  const float* __restrict__ W,
                                                  const float* __restrict__ b,
                                                  float* __restrict__ y) {
    extern __shared__ float smem[];
    float* sW    = smem;            // 128x256
    float* sfeat = smem + 32768;    // 8 warps x (16x128)

    int tid  = threadIdx.x;
    int warp = tid >> 5;
    int lane = tid & 31;

    {
        const float4* Wv = (const float4*)W;
        float4* sWv = (float4*)sW;
        for (int i = tid; i < 8192; i += 256) sWv[i] = Wv[i];
    }
    u64 bb2[4];
#pragma unroll
    for (int p = 0; p < 4; ++p) bb2[p] = pack2(b[lane * 8 + 2 * p], b[lane * 8 + 2 * p + 1]);
    __syncthreads();

    float* f = sfeat + warp * 2048;
    const float4* f4 = (const float4*)f;
    const ulonglong2* sW2 = (const ulonglong2*)sW;   // 4 floats per entry; row d = 64 entries

    for (int qg = blockIdx.x; qg < N_PTS / 8; qg += gridDim.x) {
        int q = qg * 8 + warp;

        float xi0 = x[(size_t)q * 64 + lane];
        float xi1 = x[(size_t)q * 64 + 32 + lane];
#pragma unroll 1
        for (int n = 0; n < 16; ++n) {
            int j = g_knn[q * 16 + n];
            float v0 = x[(size_t)j * 64 + lane];
            float v1 = x[(size_t)j * 64 + 32 + lane];
            f[n * 128 + lane]      = xi0;
            f[n * 128 + 32 + lane] = xi1;
            f[n * 128 + 64 + lane] = v0 - xi0;
            f[n * 128 + 96 + lane] = v1 - xi1;
        }
        __syncwarp();

        float vmax[8];
#pragma unroll
        for (int k = 0; k < 8; ++k) vmax[k] = 0.f;   // relu >= 0

#pragma unroll 1
        for (int ch = 0; ch < 4; ++ch) {             // 4 neighbors per chunk
            u64 acc[4][4];
#pragma unroll
            for (int n = 0; n < 4; ++n)
#pragma unroll
                for (int p = 0; p < 4; ++p) acc[n][p] = bb2[p];

#pragma unroll 2
            for (int d = 0; d < 128; d += 4) {
                float4 fv[4];
#pragma unroll
                for (int n = 0; n < 4; ++n)
                    fv[n] = f4[(ch * 4 + n) * 32 + (d >> 2)];   // broadcast
#pragma unroll
                for (int dd = 0; dd < 4; ++dd) {
                    ulonglong2 w0 = sW2[(d + dd) * 64 + lane * 2];      // cols 8l..8l+3
                    ulonglong2 w1 = sW2[(d + dd) * 64 + lane * 2 + 1];  // cols 8l+4..8l+7
#pragma unroll
                    for (int n = 0; n < 4; ++n) {
                        float fe = (dd == 0) ? fv[n].x : (dd == 1) ? fv[n].y
                                 : (dd == 2) ? fv[n].z : fv[n].w;
                        u64 fe2 = pack2(fe, fe);
                        ffma2(acc[n][0], fe2, w0.x);
                        ffma2(acc[n][1], fe2, w0.y);
                        ffma2(acc[n][2], fe2, w1.x);
                        ffma2(acc[n][3], fe2, w1.y);
                    }
                }
            }
#pragma unroll
            for (int n = 0; n < 4; ++n)
#pragma unroll
                for (int p = 0; p < 4; ++p) {
                    float2 v = unpack2(acc[n][p]);
                    vmax[2 * p]     = fmaxf(vmax[2 * p],     fmaxf(v.x, 0.f));
                    vmax[2 * p + 1] = fmaxf(vmax[2 * p + 1], fmaxf(v.y, 0.f));
                }
        }

        // m = lane*8+k ; c = m>>2 ; r = m&3 ; y[(q*4+r)*64 + c]
#pragma unroll
        for (int r = 0; r < 4; ++r) {
            float2 v = make_float2(vmax[r], vmax[4 + r]);
            ((float2*)(y + (size_t)(q * 4 + r) * 64))[lane] = v;
        }
        __syncwarp();
    }
}

// ---------------------------------------------------------------------------
extern "C" void kernel_launch(void* const* d_in, const int* in_sizes, int n_in,
                              void* d_out, int out_size) {
    const float* x = (const float*)d_in[0];
    const float* W = (const float*)d_in[1];
    const float* b = (const float*)d_in[2];
    float* y = (float*)d_out;

    norms_kernel<<<N_PTS / 256, 256>>>(x);
    knn_kernel<<<N_PTS / QT, QT>>>(x);

    cudaFuncSetAttribute(mlp_kernel,
                         cudaFuncAttributeMaxDynamicSharedMemorySize,
                         MLP_SMEM_FLOATS * sizeof(float));
    mlp_kernel<<<148, 256, MLP_SMEM_FLOATS * sizeof(float)>>>(x, W, b, y);
}

// round 4
// speedup vs baseline: 2.2954x; 2.2954x over previous
#include <cuda_runtime.h>
#include <math_constants.h>

#define N_PTS 16384
#define C_DIM 64
#define K_NN 16
#define SPLIT 2
#define HALF (N_PTS / SPLIT)

__device__ float g_norms[N_PTS];
__device__ int   g_knn[N_PTS * K_NN];
__device__ float g_pd[SPLIT * N_PTS * K_NN];   // partial sorted distances
__device__ int   g_pi[SPLIT * N_PTS * K_NN];   // partial sorted indices

// ---------------------------------------------------------------------------
// Kernel 0: squared norms
// ---------------------------------------------------------------------------
__global__ __launch_bounds__(256) void norms_kernel(const float* __restrict__ x) {
    int i = blockIdx.x * 256 + threadIdx.x;
    const float4* xv = (const float4*)(x + (size_t)i * C_DIM);
    float s = 0.f;
#pragma unroll
    for (int d = 0; d < 16; ++d) {
        float4 v = xv[d];
        s += v.x * v.x + v.y * v.y + v.z * v.z + v.w * v.w;
    }
    g_norms[i] = s;
}

// ---------------------------------------------------------------------------
// Kernel 1: fused distance + top-16 over HALF the candidates per CTA.
// grid = (128 query blocks, SPLIT candidate ranges); all CTAs co-resident
// -> 2 warps/SMSP, all 148 SMs busy.
// ---------------------------------------------------------------------------
#define QT 128
#define JT 128

__global__ __launch_bounds__(128) void knn_kernel(const float* __restrict__ x) {
    __shared__ float4 sc[JT * 16];   // candidate tile, 32 KB
    __shared__ float  sn[JT];

    int t = threadIdx.x;
    int q = blockIdx.x * QT + t;
    int s0 = blockIdx.y;             // candidate split

    float4 xq[16];
    const float4* xv = (const float4*)(x + (size_t)q * C_DIM);
#pragma unroll
    for (int d = 0; d < 16; ++d) xq[d] = xv[d];
    float nq = g_norms[q];

    float bd[16];
    int   bi[16];
#pragma unroll
    for (int s = 0; s < 16; ++s) { bd[s] = CUDART_INF_F; bi[s] = 0; }

    int jbeg = s0 * HALF, jend = jbeg + HALF;
    for (int jt = jbeg; jt < jend; jt += JT) {
        __syncthreads();
        const float4* src = (const float4*)(x + (size_t)jt * C_DIM);
#pragma unroll
        for (int i = 0; i < 16; ++i) sc[t + i * 128] = src[t + i * 128];
        sn[t] = g_norms[jt + t];
        __syncthreads();

#pragma unroll 1
        for (int j = 0; j < JT; ++j) {
            float a0 = 0.f, a1 = 0.f, a2 = 0.f, a3 = 0.f;
#pragma unroll
            for (int d = 0; d < 16; ++d) {
                float4 c = sc[j * 16 + d];           // broadcast across warp
                a0 = fmaf(xq[d].x, c.x, a0);
                a1 = fmaf(xq[d].y, c.y, a1);
                a2 = fmaf(xq[d].z, c.z, a2);
                a3 = fmaf(xq[d].w, c.w, a3);
            }
            float dot = (a0 + a1) + (a2 + a3);
            float d2 = nq + sn[j] - 2.0f * dot;
            int gj = jt + j;
            if (d2 < bd[15] && gj != q) {
                float cd = d2; int ci = gj;
#pragma unroll
                for (int s = 0; s < 16; ++s) {
                    if (cd < bd[s]) {
                        float td = bd[s]; bd[s] = cd; cd = td;
                        int   ti = bi[s]; bi[s] = ci; ci = ti;
                    }
                }
            }
        }
    }
    size_t base = ((size_t)s0 * N_PTS + q) * K_NN;
#pragma unroll
    for (int s = 0; s < 16; ++s) { g_pd[base + s] = bd[s]; g_pi[base + s] = bi[s]; }
}

// ---------------------------------------------------------------------------
// Kernel 1b: merge the SPLIT sorted partial lists -> final top-16 indices
// ---------------------------------------------------------------------------
__global__ __launch_bounds__(256) void merge_kernel() {
    int q = blockIdx.x * 256 + threadIdx.x;
    float da[16], db[16];
    int   ia[16], ib[16];
    size_t b0 = (size_t)q * K_NN;
    size_t b1 = ((size_t)N_PTS + q) * K_NN;
#pragma unroll
    for (int s = 0; s < 16; ++s) {
        da[s] = g_pd[b0 + s]; ia[s] = g_pi[b0 + s];
        db[s] = g_pd[b1 + s]; ib[s] = g_pi[b1 + s];
    }
    int pa = 0, pb = 0;
#pragma unroll
    for (int s = 0; s < 16; ++s) {
        bool ta = (pb >= 16) || (pa < 16 && da[pa] <= db[pb]);
        int idx; 
        if (ta) { idx = ia[pa]; ++pa; } else { idx = ib[pb]; ++pb; }
        g_knn[q * K_NN + s] = idx;
    }
}

// ---------------------------------------------------------------------------
// Kernel 2: gather + edge-MLP + relu + max over K + pixel-shuffle store.
// W resident in smem (128 KB). Warp per query; lane owns 8 output columns.
// ---------------------------------------------------------------------------
#define MLP_SMEM_FLOATS (32768 + 8 * 2048)   // W + 8 warp feat tiles

__global__ __launch_bounds__(256) void mlp_kernel(const float* __restrict__ x,
                                                  const float* __restrict__ W,
                                                  const float* __restrict__ b,
                                                  float* __restrict__ y) {
    extern __shared__ float smem[];
    float* sW    = smem;            // 128x256
    float* sfeat = smem + 32768;    // 8 warps x (16x128)

    int tid  = threadIdx.x;
    int warp = tid >> 5;
    int lane = tid & 31;

    {
        const float4* Wv = (const float4*)W;
        float4* sWv = (float4*)sW;
        for (int i = tid; i < 8192; i += 256) sWv[i] = Wv[i];
    }
    float bb[8];
#pragma unroll
    for (int k = 0; k < 8; ++k) bb[k] = b[lane * 8 + k];
    __syncthreads();

    float* f = sfeat + warp * 2048;
    const float4* f4  = (const float4*)f;
    const float4* sW4 = (const float4*)sW;

    for (int qg = blockIdx.x; qg < N_PTS / 8; qg += gridDim.x) {
        int q = qg * 8 + warp;

        float xi0 = x[(size_t)q * 64 + lane];
        float xi1 = x[(size_t)q * 64 + 32 + lane];
#pragma unroll 1
        for (int n = 0; n < 16; ++n) {
            int j = g_knn[q * 16 + n];
            float v0 = x[(size_t)j * 64 + lane];
            float v1 = x[(size_t)j * 64 + 32 + lane];
            f[n * 128 + lane]      = xi0;
            f[n * 128 + 32 + lane] = xi1;
            f[n * 128 + 64 + lane] = v0 - xi0;
            f[n * 128 + 96 + lane] = v1 - xi1;
        }
        __syncwarp();

        float vmax[8];
#pragma unroll
        for (int k = 0; k < 8; ++k) vmax[k] = 0.f;   // relu >= 0

#pragma unroll 1
        for (int ch = 0; ch < 4; ++ch) {             // 4 neighbors per chunk
            float acc[4][8];
#pragma unroll
            for (int n = 0; n < 4; ++n)
#pragma unroll
                for (int k = 0; k < 8; ++k) acc[n][k] = bb[k];

#pragma unroll 2
            for (int d = 0; d < 128; d += 4) {
                float4 fv[4];
#pragma unroll
                for (int n = 0; n < 4; ++n)
                    fv[n] = f4[(ch * 4 + n) * 32 + (d >> 2)];   // broadcast
#pragma unroll
                for (int dd = 0; dd < 4; ++dd) {
                    float4 w0 = sW4[(d + dd) * 64 + lane * 2];
                    float4 w1 = sW4[(d + dd) * 64 + lane * 2 + 1];
#pragma unroll
                    for (int n = 0; n < 4; ++n) {
                        float fe = (dd == 0) ? fv[n].x : (dd == 1) ? fv[n].y
                                 : (dd == 2) ? fv[n].z : fv[n].w;
                        acc[n][0] = fmaf(fe, w0.x, acc[n][0]);
                        acc[n][1] = fmaf(fe, w0.y, acc[n][1]);
                        acc[n][2] = fmaf(fe, w0.z, acc[n][2]);
                        acc[n][3] = fmaf(fe, w0.w, acc[n][3]);
                        acc[n][4] = fmaf(fe, w1.x, acc[n][4]);
                        acc[n][5] = fmaf(fe, w1.y, acc[n][5]);
                        acc[n][6] = fmaf(fe, w1.z, acc[n][6]);
                        acc[n][7] = fmaf(fe, w1.w, acc[n][7]);
                    }
                }
            }
#pragma unroll
            for (int n = 0; n < 4; ++n)
#pragma unroll
                for (int k = 0; k < 8; ++k)
                    vmax[k] = fmaxf(vmax[k], fmaxf(acc[n][k], 0.f));
        }

        // m = lane*8+k ; c = m>>2 ; r = m&3 ; y[(q*4+r)*64 + c]
#pragma unroll
        for (int r = 0; r < 4; ++r) {
            float2 v = make_float2(vmax[r], vmax[4 + r]);
            ((float2*)(y + (size_t)(q * 4 + r) * 64))[lane] = v;
        }
        __syncwarp();
    }
}

// ---------------------------------------------------------------------------
extern "C" void kernel_launch(void* const* d_in, const int* in_sizes, int n_in,
                              void* d_out, int out_size) {
    const float* x = (const float*)d_in[0];
    const float* W = (const float*)d_in[1];
    const float* b = (const float*)d_in[2];
    float* y = (float*)d_out;

    norms_kernel<<<N_PTS / 256, 256>>>(x);
    dim3 kgrid(N_PTS / QT, SPLIT);
    knn_kernel<<<kgrid, QT>>>(x);
    merge_kernel<<<N_PTS / 256, 256>>>();

    cudaFuncSetAttribute(mlp_kernel,
                         cudaFuncAttributeMaxDynamicSharedMemorySize,
                         MLP_SMEM_FLOATS * sizeof(float));
    mlp_kernel<<<148, 256, MLP_SMEM_FLOATS * sizeof(float)>>>(x, W, b, y);
}

// round 5
// speedup vs baseline: 2.8261x; 1.2312x over previous
#include <cuda_runtime.h>
#include <math_constants.h>

#define N_PTS 16384
#define C_DIM 64
#define K_NN 16
#define SPLIT 4
#define SEG (N_PTS / SPLIT)

__device__ float g_norms[N_PTS];
__device__ int   g_knn[N_PTS * K_NN];
__device__ float g_pd[SPLIT * N_PTS * K_NN];   // partial sorted distances
__device__ int   g_pi[SPLIT * N_PTS * K_NN];   // partial sorted indices

// ---------------------------------------------------------------------------
// Kernel 0: squared norms
// ---------------------------------------------------------------------------
__global__ __launch_bounds__(256) void norms_kernel(const float* __restrict__ x) {
    int i = blockIdx.x * 256 + threadIdx.x;
    const float4* xv = (const float4*)(x + (size_t)i * C_DIM);
    float s = 0.f;
#pragma unroll
    for (int d = 0; d < 16; ++d) {
        float4 v = xv[d];
        s += v.x * v.x + v.y * v.y + v.z * v.z + v.w * v.w;
    }
    g_norms[i] = s;
}

// ---------------------------------------------------------------------------
// Kernel 1: fused distance + top-16 over N/SPLIT candidates per CTA.
// grid = (128, SPLIT) = 512 CTAs, all co-resident -> 3-4 warps/SMSP.
// ---------------------------------------------------------------------------
#define QT 128
#define JT 128

__global__ __launch_bounds__(128) void knn_kernel(const float* __restrict__ x) {
    __shared__ float4 sc[JT * 16];   // candidate tile, 32 KB
    __shared__ float  sn[JT];

    int t = threadIdx.x;
    int q = blockIdx.x * QT + t;
    int s0 = blockIdx.y;             // candidate split

    float4 xq[16];
    const float4* xv = (const float4*)(x + (size_t)q * C_DIM);
#pragma unroll
    for (int d = 0; d < 16; ++d) xq[d] = xv[d];
    float nq = g_norms[q];

    float bd[16];
    int   bi[16];
#pragma unroll
    for (int s = 0; s < 16; ++s) { bd[s] = CUDART_INF_F; bi[s] = 0; }

    int jbeg = s0 * SEG, jend = jbeg + SEG;
    for (int jt = jbeg; jt < jend; jt += JT) {
        __syncthreads();
        const float4* src = (const float4*)(x + (size_t)jt * C_DIM);
#pragma unroll
        for (int i = 0; i < 16; ++i) sc[t + i * 128] = src[t + i * 128];
        sn[t] = g_norms[jt + t];
        __syncthreads();

#pragma unroll 1
        for (int j = 0; j < JT; ++j) {
            float a0 = 0.f, a1 = 0.f, a2 = 0.f, a3 = 0.f;
#pragma unroll
            for (int d = 0; d < 16; ++d) {
                float4 c = sc[j * 16 + d];           // broadcast across warp
                a0 = fmaf(xq[d].x, c.x, a0);
                a1 = fmaf(xq[d].y, c.y, a1);
                a2 = fmaf(xq[d].z, c.z, a2);
                a3 = fmaf(xq[d].w, c.w, a3);
            }
            float dot = (a0 + a1) + (a2 + a3);
            float d2 = nq + sn[j] - 2.0f * dot;
            int gj = jt + j;
            if (d2 < bd[15] && gj != q) {
                float cd = d2; int ci = gj;
#pragma unroll
                for (int s = 0; s < 16; ++s) {
                    if (cd < bd[s]) {
                        float td = bd[s]; bd[s] = cd; cd = td;
                        int   ti = bi[s]; bi[s] = ci; ci = ti;
                    }
                }
            }
        }
    }
    size_t base = ((size_t)s0 * N_PTS + q) * K_NN;
#pragma unroll
    for (int s = 0; s < 16; ++s) { g_pd[base + s] = bd[s]; g_pi[base + s] = bi[s]; }
}

// ---------------------------------------------------------------------------
// Kernel 1b: 4-way merge of sorted partial lists -> final top-16 indices
// ---------------------------------------------------------------------------
__global__ __launch_bounds__(256) void merge_kernel() {
    int q = blockIdx.x * 256 + threadIdx.x;
    float d[SPLIT][16];
    int   id[SPLIT][16];
#pragma unroll
    for (int l = 0; l < SPLIT; ++l) {
        size_t b = ((size_t)l * N_PTS + q) * K_NN;
#pragma unroll
        for (int s = 0; s < 16; ++s) { d[l][s] = g_pd[b + s]; id[l][s] = g_pi[b + s]; }
    }
    int p[SPLIT] = {0, 0, 0, 0};
#pragma unroll
    for (int s = 0; s < 16; ++s) {
        float best = CUDART_INF_F; int bl = 0;
#pragma unroll
        for (int l = 0; l < SPLIT; ++l) {
            float v = (p[l] < 16) ? d[l][p[l]] : CUDART_INF_F;
            if (v < best) { best = v; bl = l; }
        }
        g_knn[q * K_NN + s] = id[bl][p[bl]];
        ++p[bl];
    }
}

// ---------------------------------------------------------------------------
// Kernel 2: gather + edge-MLP + relu + max over K + pixel-shuffle store.
// W resident in smem; warp per query; lane owns 8 output columns;
// 8-neighbor register tile halves weight-LDS traffic vs R4.
// ---------------------------------------------------------------------------
#define MLP_SMEM_FLOATS (32768 + 8 * 2048)   // W(128x256) + 8 warp feat tiles

__global__ __launch_bounds__(256) void mlp_kernel(const float* __restrict__ x,
                                                  const float* __restrict__ W,
                                                  const float* __restrict__ b,
                                                  float* __restrict__ y) {
    extern __shared__ float smem[];
    float* sW    = smem;            // 128x256
    float* sfeat = smem + 32768;    // 8 warps x (16x128)

    int tid  = threadIdx.x;
    int warp = tid >> 5;
    int lane = tid & 31;

    {
        const float4* Wv = (const float4*)W;
        float4* sWv = (float4*)sW;
        for (int i = tid; i < 8192; i += 256) sWv[i] = Wv[i];
    }
    float bb[8];
#pragma unroll
    for (int k = 0; k < 8; ++k) bb[k] = b[lane * 8 + k];
    __syncthreads();

    float* f = sfeat + warp * 2048;
    const float4* f4  = (const float4*)f;
    const float4* sW4 = (const float4*)sW;

    for (int qg = blockIdx.x; qg < N_PTS / 8; qg += gridDim.x) {
        int q = qg * 8 + warp;

        float xi0 = x[(size_t)q * 64 + lane];
        float xi1 = x[(size_t)q * 64 + 32 + lane];
#pragma unroll 1
        for (int n = 0; n < 16; ++n) {
            int j = g_knn[q * 16 + n];
            float v0 = x[(size_t)j * 64 + lane];
            float v1 = x[(size_t)j * 64 + 32 + lane];
            f[n * 128 + lane]      = xi0;
            f[n * 128 + 32 + lane] = xi1;
            f[n * 128 + 64 + lane] = v0 - xi0;
            f[n * 128 + 96 + lane] = v1 - xi1;
        }
        __syncwarp();

        float vmax[8];
#pragma unroll
        for (int k = 0; k < 8; ++k) vmax[k] = 0.f;   // relu >= 0

#pragma unroll 1
        for (int ch = 0; ch < 2; ++ch) {             // 8 neighbors per chunk
            float acc[8][8];
#pragma unroll
            for (int n = 0; n < 8; ++n)
#pragma unroll
                for (int k = 0; k < 8; ++k) acc[n][k] = bb[k];

#pragma unroll 1
            for (int d = 0; d < 128; d += 4) {
                float4 fv[8];
#pragma unroll
                for (int n = 0; n < 8; ++n)
                    fv[n] = f4[(ch * 8 + n) * 32 + (d >> 2)];   // broadcast
#pragma unroll
                for (int dd = 0; dd < 4; ++dd) {
                    float4 w0 = sW4[(d + dd) * 64 + lane * 2];
                    float4 w1 = sW4[(d + dd) * 64 + lane * 2 + 1];
#pragma unroll
                    for (int n = 0; n < 8; ++n) {
                        float fe = (dd == 0) ? fv[n].x : (dd == 1) ? fv[n].y
                                 : (dd == 2) ? fv[n].z : fv[n].w;
                        acc[n][0] = fmaf(fe, w0.x, acc[n][0]);
                        acc[n][1] = fmaf(fe, w0.y, acc[n][1]);
                        acc[n][2] = fmaf(fe, w0.z, acc[n][2]);
                        acc[n][3] = fmaf(fe, w0.w, acc[n][3]);
                        acc[n][4] = fmaf(fe, w1.x, acc[n][4]);
                        acc[n][5] = fmaf(fe, w1.y, acc[n][5]);
                        acc[n][6] = fmaf(fe, w1.z, acc[n][6]);
                        acc[n][7] = fmaf(fe, w1.w, acc[n][7]);
                    }
                }
            }
#pragma unroll
            for (int n = 0; n < 8; ++n)
#pragma unroll
                for (int k = 0; k < 8; ++k)
                    vmax[k] = fmaxf(vmax[k], fmaxf(acc[n][k], 0.f));
        }

        // m = lane*8+k ; c = m>>2 ; r = m&3 ; y[(q*4+r)*64 + c]
#pragma unroll
        for (int r = 0; r < 4; ++r) {
            float2 v = make_float2(vmax[r], vmax[4 + r]);
            ((float2*)(y + (size_t)(q * 4 + r) * 64))[lane] = v;
        }
        __syncwarp();
    }
}

// ---------------------------------------------------------------------------
extern "C" void kernel_launch(void* const* d_in, const int* in_sizes, int n_in,
                              void* d_out, int out_size) {
    const float* x = (const float*)d_in[0];
    const float* W = (const float*)d_in[1];
    const float* b = (const float*)d_in[2];
    float* y = (float*)d_out;

    norms_kernel<<<N_PTS / 256, 256>>>(x);
    dim3 kgrid(N_PTS / QT, SPLIT);
    knn_kernel<<<kgrid, QT>>>(x);
    merge_kernel<<<N_PTS / 256, 256>>>();

    cudaFuncSetAttribute(mlp_kernel,
                         cudaFuncAttributeMaxDynamicSharedMemorySize,
                         MLP_SMEM_FLOATS * sizeof(float));
    mlp_kernel<<<148, 256, MLP_SMEM_FLOATS * sizeof(float)>>>(x, W, b, y);
}